// round 3
// baseline (speedup 1.0000x reference)
#include <cuda_runtime.h>
#include <cuda_bf16.h>

#define NSIDE 256
#define NB    256
#define LAM   0.05f   // STEP = ALPHA/2
#define TOLV  0.01f
#define NITER 35

// Cross-block exchange buffers.
__device__ float g_y [NSIDE * NSIDE];
__device__ float g_xT[NSIDE * NSIDE];

// Flag-array grid barrier state (zero-init at load; epochs are monotone and
// compared relatively, so state self-carries across graph replays).
__device__ volatile unsigned g_flag[NB * 8];   // one padded slot per block
__device__ volatile float    g_res [NB * 8];   // per-block residual max
__device__ volatile unsigned g_ep;             // release word; +0x40000000 encodes "stop"

// Exact 1D TV prox (Condat 2013). Single thread over SMEM line y (padded to
// NSIDE+2). Fast path keeps segment restarts entirely in registers; divisions
// replaced by exactly-rounded reciprocal table lookups.
__device__ __forceinline__ void tv1d(const float* __restrict__ y,
                                     float* __restrict__ x,
                                     const float* __restrict__ rcp_s)
{
    const float lam = LAM, mlam = -LAM, twolam = 2.0f * LAM;
    int k = 0, k0 = 0, kminus = 0, kplus = 0;
    float vmin = y[0] - lam, vmax = y[0] + lam;
    float umin = lam, umax = mlam;
    float ynext = y[1];
    for (;;) {
        while (k == NSIDE - 1) {
            if (umin < 0.0f) {
                do { x[k0++] = vmin; } while (k0 <= kminus);
                k = k0; kminus = k0;
                vmin = y[k];
                umin = lam;
                umax = vmin + lam - vmax;
            } else if (umax > 0.0f) {
                do { x[k0++] = vmax; } while (k0 <= kplus);
                k = k0; kplus = k0;
                vmax = y[k];
                umax = mlam;
                umin = vmax - lam - vmin;
            } else {
                vmin += umin * rcp_s[k - k0];           // /(k-k0+1)
                do { x[k0++] = vmin; } while (k0 <= k);
                return;
            }
            ynext = y[k + 1];   // padded read, safe
        }
        float yspec = y[k + 2];                 // speculative prefetch (padded)
        float a  = umin + (ynext - vmin);       // candidate umin'
        float bb = umax + (ynext - vmax);       // candidate umax'
        if (a < mlam) {                         // negative jump
            do { x[k0++] = vmin; } while (k0 <= kminus);
            bool fast = (k0 == k + 1);          // restart at current ynext?
            k = k0; kminus = k0; kplus = k0;
            float nv;
            if (fast) { nv = ynext; ynext = yspec; }
            else      { nv = y[k0]; ynext = y[k0 + 1]; }
            vmin = nv; vmax = nv + twolam;
            umin = lam; umax = mlam;
        } else if (bb > lam) {                  // positive jump
            do { x[k0++] = vmax; } while (k0 <= kplus);
            bool fast = (k0 == k + 1);
            k = k0; kminus = k0; kplus = k0;
            float nv;
            if (fast) { nv = ynext; ynext = yspec; }
            else      { nv = y[k0]; ynext = y[k0 + 1]; }
            vmax = nv; vmin = nv - twolam;
            umin = lam; umax = mlam;
        } else {                                // no jump
            k++;
            umin = a; umax = bb;
            if (a >= lam)   { vmin += (a - lam)  * rcp_s[k - k0]; umin = lam;  kminus = k; }
            if (bb <= mlam) { vmax += (bb + lam) * rcp_s[k - k0]; umax = mlam; kplus  = k; }
            ynext = yspec;
        }
    }
}

// Flag-array grid barrier. Every block: one uncontended flag store. Block 0's
// warp polls all flags, reduces residuals (commit barriers), publishes release
// + stop decision in g_ep. Returns true if DR converged (commit barriers only).
__device__ __forceinline__ bool gridbar(int b, int lane, unsigned& ep,
                                        bool commit, float m)
{
    ep += 1;
    __syncwarp();
    if (lane == 0) {
        __threadfence();                 // publish this block's gmem writes
        if (commit) g_res[b * 8] = m;
        g_flag[b * 8] = ep;
    }
    bool stop = false;
    if (b == 0) {
        // leader: all 32 lanes poll 8 flags each
        for (;;) {
            bool ok = true;
#pragma unroll
            for (int t = 0; t < 8; t++) {
                unsigned f = g_flag[(lane + t * 32) * 8];
                ok &= ((int)(f - ep) >= 0);
            }
            if (__all_sync(0xffffffffu, ok)) break;
        }
        float mm = 0.0f;
        if (commit) {
#pragma unroll
            for (int t = 0; t < 8; t++)
                mm = fmaxf(mm, g_res[(lane + t * 32) * 8]);
#pragma unroll
            for (int off = 16; off; off >>= 1)
                mm = fmaxf(mm, __shfl_xor_sync(0xffffffffu, mm, off));
            stop = (mm < TOLV);
        }
        if (lane == 0) {
            __threadfence();
            g_ep = ep + (stop ? 0x40000000u : 0u);
        }
        __syncwarp();
    } else {
        unsigned seen = 0;
        if (lane == 0) {
            do { seen = g_ep; } while ((int)(seen - ep) < 0);
            __threadfence();             // acquire for cross-block data
        }
        seen = __shfl_sync(0xffffffffu, seen, 0);
        stop = ((seen - ep) >= 0x40000000u);
    }
    __syncwarp();
    return stop;
}

__global__ void __launch_bounds__(32)
tv2d_persistent(const float* __restrict__ X, float* __restrict__ x)
{
    __shared__ float s[NSIDE + 2], o[NSIDE], p[NSIDE], q[NSIDE], rcp_s[NSIDE];
    const int b = blockIdx.x;
    const int lane = threadIdx.x;
    unsigned ep = g_ep;   // stable at launch: no release can occur before all blocks start

#pragma unroll
    for (int t = 0; t < NSIDE / 32; t++) {
        int i = lane + t * 32;
        p[i] = 0.0f;
        q[i] = 0.0f;
        rcp_s[i] = 1.0f / (float)(i + 1);
    }
    if (lane == 0) { s[NSIDE] = 0.0f; s[NSIDE + 1] = 0.0f; }

    for (int it = 0; it < NITER; it++) {
        // ---- column phase: block b owns column b ----
#pragma unroll
        for (int t = 0; t < NSIDE / 32; t++) {
            int i = lane + t * 32;
            float xv = (it == 0) ? X[i * NSIDE + b] : __ldcg(&g_xT[b * NSIDE + i]);
            s[i] = xv + p[i];
        }
        __syncwarp();
        if (lane == 0) tv1d(s, o, rcp_s);
        __syncwarp();
#pragma unroll
        for (int t = 0; t < NSIDE / 32; t++) {
            int i = lane + t * 32;
            float ov = o[i];
            p[i] = s[i] - ov;
            g_y[i * NSIDE + b] = ov;      // strided column write
        }
        gridbar(b, lane, ep, false, 0.0f);

        // ---- row phase: block b owns row b ----
#pragma unroll
        for (int t = 0; t < NSIDE / 32; t++) {
            int i = lane + t * 32;
            s[i] = __ldcg(&g_y[b * NSIDE + i]) + q[i];
        }
        __syncwarp();
        if (lane == 0) tv1d(s, o, rcp_s);
        __syncwarp();

        float m = 0.0f;
#pragma unroll
        for (int t = 0; t < NSIDE / 32; t++) {
            int i = lane + t * 32;
            float ov = o[i];
            float sv = s[i];
            float qo = q[i];
            q[i] = sv - ov;
            x[b * NSIDE + i] = ov;         // d_out (coalesced)
            g_xT[i * NSIDE + b] = ov;      // transposed mirror for next col phase
            m = fmaxf(m, fabsf((sv - qo) - ov));   // |y - x2|
        }
#pragma unroll
        for (int off = 16; off; off >>= 1)
            m = fmaxf(m, __shfl_xor_sync(0xffffffffu, m, off));

        if (gridbar(b, lane, ep, true, m)) break;   // DR converged
    }
}

extern "C" void kernel_launch(void* const* d_in, const int* in_sizes, int n_in,
                              void* d_out, int out_size)
{
    const float* X = (const float*)d_in[0];
    float* x = (float*)d_out;
    tv2d_persistent<<<NB, 32>>>(X, x);
}

// round 4
// speedup vs baseline: 2.0385x; 2.0385x over previous
#include <cuda_runtime.h>
#include <cuda_bf16.h>

#define NSIDE 256
#define NB    256
#define NT    64      // 2 warps: warp0 scans forward, warp1 scans backward
#define LAM   0.05f   // STEP = ALPHA/2
#define TOLV  0.01f
#define NITER 35

// Cross-block exchange buffers.
__device__ float g_y [NSIDE * NSIDE];
__device__ float g_xT[NSIDE * NSIDE];

// Atomic grid barrier (R2 design — measured faster than flag-array).
__device__ unsigned          g_cnt;
__device__ volatile unsigned g_ep;
__device__ volatile int      g_stop;
__device__ int               g_accbits;

struct TVState {
    int k, k0, kminus, kplus;
    float vmin, vmax, umin, umax, ynext;
};

template<bool FWD>
__device__ __forceinline__ float ldy(const float* __restrict__ s, int i) {
    return FWD ? s[i] : s[NSIDE - 1 - i];
}
template<bool FWD>
__device__ __forceinline__ void sto(float* __restrict__ out, int i, float v) {
    if (FWD) out[i] = v; else out[NSIDE - 1 - i] = v;
}

// Exact 1D TV prox (Condat 2013), resumable. Runs until k >= kstop (phase
// boundary) or emission frontier k0 >= k0stop, or full completion (termination
// block at k == NSIDE-1, only reachable when kstop == NSIDE). State persists
// in `t` across calls. s padded to NSIDE+2 (forward reads s[k+2] up to s[257]).
template<bool FWD>
__device__ void tv_scan(const float* __restrict__ s, float* __restrict__ out,
                        const float* __restrict__ rcp, TVState& t,
                        int kstop, int k0stop)
{
    const float lam = LAM, mlam = -LAM, twolam = 2.0f * LAM;
    for (;;) {
        if (t.k0 >= k0stop) return;
        while (t.k == NSIDE - 1) {          // termination (kstop==NSIDE only)
            if (t.umin < 0.0f) {
                do { sto<FWD>(out, t.k0++, t.vmin); } while (t.k0 <= t.kminus);
                t.k = t.k0; t.kminus = t.k0;
                t.vmin = ldy<FWD>(s, t.k);
                t.umin = lam;
                t.umax = t.vmin + lam - t.vmax;
            } else if (t.umax > 0.0f) {
                do { sto<FWD>(out, t.k0++, t.vmax); } while (t.k0 <= t.kplus);
                t.k = t.k0; t.kplus = t.k0;
                t.vmax = ldy<FWD>(s, t.k);
                t.umax = mlam;
                t.umin = t.vmax - lam - t.vmin;
            } else {
                t.vmin += t.umin * rcp[t.k - t.k0];
                do { sto<FWD>(out, t.k0++, t.vmin); } while (t.k0 <= t.k);
                t.k0 = NSIDE + 4;            // done
                return;
            }
            t.ynext = ldy<FWD>(s, t.k + 1);
            if (t.k0 >= k0stop) return;
        }
        if (t.k >= kstop) return;           // phase boundary
        float yspec = ldy<FWD>(s, t.k + 2); // speculative prefetch (padded)
        float a  = t.umin + (t.ynext - t.vmin);
        float bb = t.umax + (t.ynext - t.vmax);
        if (a < mlam) {                     // negative jump
            do { sto<FWD>(out, t.k0++, t.vmin); } while (t.k0 <= t.kminus);
            bool fast = (t.k0 == t.k + 1);  // restart value already in ynext?
            t.k = t.k0; t.kminus = t.k0; t.kplus = t.k0;
            float nv = fast ? t.ynext : ldy<FWD>(s, t.k0);
            t.ynext  = fast ? yspec   : ldy<FWD>(s, t.k0 + 1);
            t.vmin = nv; t.vmax = nv + twolam;
            t.umin = lam; t.umax = mlam;
        } else if (bb > lam) {              // positive jump
            do { sto<FWD>(out, t.k0++, t.vmax); } while (t.k0 <= t.kplus);
            bool fast = (t.k0 == t.k + 1);
            t.k = t.k0; t.kminus = t.k0; t.kplus = t.k0;
            float nv = fast ? t.ynext : ldy<FWD>(s, t.k0);
            t.ynext  = fast ? yspec   : ldy<FWD>(s, t.k0 + 1);
            t.vmax = nv; t.vmin = nv - twolam;
            t.umin = lam; t.umax = mlam;
        } else {                            // no jump
            t.k++;
            t.umin = a; t.umax = bb;
            if (a >= lam)   { t.vmin += (a - lam)  * rcp[t.k - t.k0]; t.umin = lam;  t.kminus = t.k; }
            if (bb <= mlam) { t.vmax += (bb + lam) * rcp[t.k - t.k0]; t.umax = mlam; t.kplus  = t.k; }
            t.ynext = yspec;
        }
    }
}

__device__ __forceinline__ void init_state(const float* __restrict__ s, TVState& t, bool fwd)
{
    float y0 = fwd ? s[0] : s[NSIDE - 1];
    float y1 = fwd ? s[1] : s[NSIDE - 2];
    t.k = 0; t.k0 = 0; t.kminus = 0; t.kplus = 0;
    t.vmin = y0 - LAM; t.vmax = y0 + LAM;
    t.umin = LAM; t.umax = -LAM;
    t.ynext = y1;
}

// Grid barrier (R2 design). All threads fence after release so later plain
// global loads observe other blocks' pre-barrier writes.
__device__ __forceinline__ void gridbar(unsigned& ep, bool doCommit)
{
    __syncthreads();
    ep += 1;
    if (threadIdx.x == 0) {
        __threadfence();
        unsigned old = atomicAdd(&g_cnt, 1u);
        if (old == NB - 1) {
            __threadfence();
            if (doCommit) {
                g_stop = (__int_as_float(g_accbits) < TOLV) ? 1 : 0;
                g_accbits = 0;
            }
            atomicExch(&g_cnt, 0u);
            __threadfence();
            g_ep = ep;
        } else {
            while ((int)(g_ep - ep) < 0) { }
        }
    }
    __syncthreads();
    __threadfence();
}

__global__ void __launch_bounds__(NT)
tv2d_persistent(const float* __restrict__ X, float* __restrict__ x)
{
    __shared__ float s[NSIDE + 2], o[NSIDE], ob[NSIDE];
    __shared__ float p[NSIDE], q[NSIDE], rcp_s[NSIDE];
    __shared__ int   se_b;
    __shared__ float swm[2];
    const int b = blockIdx.x;
    const int tid = threadIdx.x;
    const int lane = tid & 31;
    const int wid = tid >> 5;
    unsigned ep = g_ep;
    TVState tf, tb;

#pragma unroll
    for (int t = 0; t < NSIDE / NT; t++) {
        int i = tid + t * NT;
        p[i] = 0.0f;
        q[i] = 0.0f;
        rcp_s[i] = 1.0f / (float)(i + 1);
    }
    if (tid == 0) { s[NSIDE] = 0.0f; s[NSIDE + 1] = 0.0f; }

    for (int it = 0; it < NITER; it++) {
        // ================= column phase: block b owns column b =============
#pragma unroll
        for (int t = 0; t < NSIDE / NT; t++) {
            int i = tid + t * NT;
            float xv = (it == 0) ? X[i * NSIDE + b] : g_xT[b * NSIDE + i];
            s[i] = xv + p[i];
        }
        __syncthreads();
        if (tid == 0) {                      // forward half-scan (warp 0)
            init_state(s, tf, true);
            tv_scan<true>(s, o, rcp_s, tf, NSIDE / 2, NSIDE + 4);
        } else if (tid == 32) {              // backward half-scan (warp 1)
            init_state(s, tb, false);
            tv_scan<false>(s, ob, rcp_s, tb, NSIDE / 2, NSIDE + 4);
            se_b = NSIDE - tb.k0;            // positions >= se_b final in ob
        }
        __syncthreads();
        if (tid == 0)                        // gap fixup: forward continues
            tv_scan<true>(s, o, rcp_s, tf, NSIDE, se_b);
        __syncthreads();
        {
            int eb = se_b;
#pragma unroll
            for (int t = 0; t < NSIDE / NT; t++) {
                int i = tid + t * NT;
                float ov = (i >= eb) ? ob[i] : o[i];
                p[i] = s[i] - ov;
                g_y[i * NSIDE + b] = ov;     // strided column write
            }
        }
        gridbar(ep, false);

        // ================= row phase: block b owns row b ===================
#pragma unroll
        for (int t = 0; t < NSIDE / NT; t++) {
            int i = tid + t * NT;
            s[i] = g_y[b * NSIDE + i] + q[i];
        }
        __syncthreads();
        if (tid == 0) {
            init_state(s, tf, true);
            tv_scan<true>(s, o, rcp_s, tf, NSIDE / 2, NSIDE + 4);
        } else if (tid == 32) {
            init_state(s, tb, false);
            tv_scan<false>(s, ob, rcp_s, tb, NSIDE / 2, NSIDE + 4);
            se_b = NSIDE - tb.k0;
        }
        __syncthreads();
        if (tid == 0)
            tv_scan<true>(s, o, rcp_s, tf, NSIDE, se_b);
        __syncthreads();

        float m = 0.0f;
        {
            int eb = se_b;
#pragma unroll
            for (int t = 0; t < NSIDE / NT; t++) {
                int i = tid + t * NT;
                float ov = (i >= eb) ? ob[i] : o[i];
                float sv = s[i];
                float qo = q[i];
                q[i] = sv - ov;
                x[b * NSIDE + i] = ov;       // d_out (coalesced)
                g_xT[i * NSIDE + b] = ov;    // transposed mirror
                m = fmaxf(m, fabsf((sv - qo) - ov));   // |y - x2|
            }
        }
#pragma unroll
        for (int off = 16; off; off >>= 1)
            m = fmaxf(m, __shfl_xor_sync(0xffffffffu, m, off));
        if (lane == 0) swm[wid] = m;
        __syncthreads();
        if (tid == 0) {
            float mm = fmaxf(swm[0], swm[1]);
            atomicMax(&g_accbits, __float_as_int(mm));  // nonneg: int order OK
        }

        gridbar(ep, true);
        if (g_stop) break;                   // DR converged
    }
}

extern "C" void kernel_launch(void* const* d_in, const int* in_sizes, int n_in,
                              void* d_out, int out_size)
{
    const float* X = (const float*)d_in[0];
    float* x = (float*)d_out;
    tv2d_persistent<<<NB, NT>>>(X, x);
}

// round 6
// speedup vs baseline: 2.7209x; 1.3348x over previous
#include <cuda_runtime.h>
#include <cuda_bf16.h>

#define NSIDE 256
#define NB    256
#define NT    128     // 4 scanner threads in 4 different warps
#define LAM   0.05f   // STEP = ALPHA/2
#define TOLV  0.01f
#define NITER 35
#define HALF  (NSIDE / 2)
#define QTR   (NSIDE / 4)
#define BIGK  (NSIDE + 8)

// Cross-block exchange buffers.
__device__ float g_y [NSIDE * NSIDE];
__device__ float g_xT[NSIDE * NSIDE];

// Atomic grid barrier.
__device__ unsigned          g_cnt;
__device__ volatile unsigned g_ep;
__device__ volatile int      g_stop;
__device__ int               g_accbits;

struct TVState {
    int k, k0, kminus, kplus;
    float vmin, vmax, umin, umax, ynext;
};

template<bool FWD>
__device__ __forceinline__ float ldy(const float* __restrict__ s, int i) {
    return FWD ? s[i] : s[NSIDE - 1 - i];
}
template<bool FWD>
__device__ __forceinline__ void sto(float* __restrict__ out, int i, float v) {
    if (FWD) out[i] = v; else out[NSIDE - 1 - i] = v;
}

// Fresh Condat state positioned at `pos` (pos < NSIDE-1).
template<bool FWD>
__device__ __forceinline__ void init_state_at(const float* __restrict__ s,
                                              TVState& t, int pos)
{
    float y0 = ldy<FWD>(s, pos), y1 = ldy<FWD>(s, pos + 1);
    t.k = pos; t.k0 = pos; t.kminus = pos; t.kplus = pos;
    t.vmin = y0 - LAM; t.vmax = y0 + LAM;
    t.umin = LAM; t.umax = -LAM;
    t.ynext = y1;
}

// Exact 1D TV prox (Condat 2013), resumable.
// MODE 0: plain. MODE 1: record restart (pos,dir) into log.
// MODE 2: after each restart, check log; if log[k0]==dir the state provably
//         equals the speculative scanner's post-restart state -> return 1.
// Stops when k >= kstop or emission frontier k0 >= k0stop (or completion).
template<bool FWD, int MODE>
__device__ int tv_scan(const float* __restrict__ s, float* __restrict__ out,
                       const float* __restrict__ rcp, TVState& t,
                       int kstop, int k0stop, unsigned char* log)
{
    const float lam = LAM, mlam = -LAM, twolam = 2.0f * LAM;
    for (;;) {
        if (t.k0 >= k0stop) return 0;
        while (t.k == NSIDE - 1) {            // termination (kstop==NSIDE only)
            if (t.umin < 0.0f) {
                do { sto<FWD>(out, t.k0++, t.vmin); } while (t.k0 <= t.kminus);
                t.k = t.k0; t.kminus = t.k0;
                t.vmin = ldy<FWD>(s, t.k);
                t.umin = lam;
                t.umax = t.vmin + lam - t.vmax;
            } else if (t.umax > 0.0f) {
                do { sto<FWD>(out, t.k0++, t.vmax); } while (t.k0 <= t.kplus);
                t.k = t.k0; t.kplus = t.k0;
                t.vmax = ldy<FWD>(s, t.k);
                t.umax = mlam;
                t.umin = t.vmax - lam - t.vmin;
            } else {
                t.vmin += t.umin * rcp[t.k - t.k0];
                do { sto<FWD>(out, t.k0++, t.vmin); } while (t.k0 <= t.k);
                t.k0 = BIGK;                   // done
                return 0;
            }
            t.ynext = ldy<FWD>(s, t.k + 1);
            if (t.k0 >= k0stop) return 0;
        }
        if (t.k >= kstop) return 0;
        float yspec = ldy<FWD>(s, t.k + 2);   // speculative prefetch (padded)
        float a  = t.umin + (t.ynext - t.vmin);
        float bb = t.umax + (t.ynext - t.vmax);
        if (a < mlam) {                       // negative jump
            do { sto<FWD>(out, t.k0++, t.vmin); } while (t.k0 <= t.kminus);
            bool fast = (t.k0 == t.k + 1);
            t.k = t.k0; t.kminus = t.k0; t.kplus = t.k0;
            float nv = fast ? t.ynext : ldy<FWD>(s, t.k0);
            t.ynext  = fast ? yspec   : ldy<FWD>(s, t.k0 + 1);
            t.vmin = nv; t.vmax = nv + twolam;
            t.umin = lam; t.umax = mlam;
            if (MODE == 1) log[t.k0] = 1;
            if (MODE == 2) { if (log[t.k0] == 1) return 1; }
        } else if (bb > lam) {                // positive jump
            do { sto<FWD>(out, t.k0++, t.vmax); } while (t.k0 <= t.kplus);
            bool fast = (t.k0 == t.k + 1);
            t.k = t.k0; t.kminus = t.k0; t.kplus = t.k0;
            float nv = fast ? t.ynext : ldy<FWD>(s, t.k0);
            t.ynext  = fast ? yspec   : ldy<FWD>(s, t.k0 + 1);
            t.vmax = nv; t.vmin = nv - twolam;
            t.umin = lam; t.umax = mlam;
            if (MODE == 1) log[t.k0] = 2;
            if (MODE == 2) { if (log[t.k0] == 2) return 1; }
        } else {                              // no jump
            t.k++;
            t.umin = a; t.umax = bb;
            if (a >= lam)   { t.vmin += (a - lam)  * rcp[t.k - t.k0]; t.umin = lam;  t.kminus = t.k; }
            if (bb <= mlam) { t.vmax += (bb + lam) * rcp[t.k - t.k0]; t.umax = mlam; t.kplus  = t.k; }
            t.ynext = yspec;
        }
    }
}

// Grid barrier (R2 atomic design — measured best).
__device__ __forceinline__ void gridbar(unsigned& ep, bool doCommit)
{
    __syncthreads();
    ep += 1;
    if (threadIdx.x == 0) {
        __threadfence();
        unsigned old = atomicAdd(&g_cnt, 1u);
        if (old == NB - 1) {
            __threadfence();
            if (doCommit) {
                g_stop = (__int_as_float(g_accbits) < TOLV) ? 1 : 0;
                g_accbits = 0;
            }
            atomicExch(&g_cnt, 0u);
            __threadfence();
            g_ep = ep;
        } else {
            while ((int)(g_ep - ep) < 0) { }
        }
    }
    __syncthreads();
    __threadfence();
}

struct SharedBlk {
    float s[NSIDE + 2];
    float o[NSIDE];
    float ob[NSIDE];
    float p[NSIDE];
    float q[NSIDE];
    float rcp_s[NSIDE];
    unsigned char f_log[NSIDE + 2];
    unsigned char b_log[NSIDE + 2];
    TVState sf_end, sb_end;
    int   se_b;
    float swm[NT / 32];
};

// One full line solve: s (padded) -> merged o/ob, returns eb via sh.se_b.
// Uses 4 scanner threads (tids 0,32,64,96).
__device__ __forceinline__ void solve_line(SharedBlk& sh, int tid,
                                           TVState& tf, TVState& tb)
{
    // ---- stage A: four parallel scans ----
    if (tid == 0) {                       // exact forward on [0, QTR)
        init_state_at<true>(sh.s, tf, 0);
        tv_scan<true, 0>(sh.s, sh.o, sh.rcp_s, tf, QTR, BIGK, 0);
    } else if (tid == 32) {               // speculative forward on [QTR, HALF)
        TVState t; init_state_at<true>(sh.s, t, QTR);
        tv_scan<true, 1>(sh.s, sh.o, sh.rcp_s, t, HALF, BIGK, sh.f_log);
        sh.sf_end = t;
    } else if (tid == 64) {               // exact backward on [0, QTR)b
        init_state_at<false>(sh.s, tb, 0);
        tv_scan<false, 0>(sh.s, sh.ob, sh.rcp_s, tb, QTR, BIGK, 0);
    } else if (tid == 96) {               // speculative backward on [QTR, HALF)b
        TVState t; init_state_at<false>(sh.s, t, QTR);
        tv_scan<false, 1>(sh.s, sh.ob, sh.rcp_s, t, HALF, BIGK, sh.b_log);
        sh.sb_end = t;
    }
    __syncthreads();

    // ---- stage B: coupling fixups (forward & backward concurrently) ----
    if (tid == 0) {
        if (tv_scan<true, 2>(sh.s, sh.o, sh.rcp_s, tf, HALF, BIGK, sh.f_log))
            tf = sh.sf_end;               // coupled: adopt speculative tail
    } else if (tid == 64) {
        if (tv_scan<false, 2>(sh.s, sh.ob, sh.rcp_s, tb, HALF, BIGK, sh.b_log))
            tb = sh.sb_end;
        sh.se_b = NSIDE - tb.k0;          // first finalized backward position
    }
    __syncthreads();

    // ---- stage C: forward closes the middle gap ----
    if (tid == 0)
        tv_scan<true, 0>(sh.s, sh.o, sh.rcp_s, tf, NSIDE, sh.se_b, 0);
    __syncthreads();
}

__global__ void __launch_bounds__(NT)
tv2d_persistent(const float* __restrict__ X, float* __restrict__ x)
{
    __shared__ SharedBlk sh;
    const int b = blockIdx.x;
    const int tid = threadIdx.x;
    const int lane = tid & 31;
    const int wid = tid >> 5;
    unsigned ep = g_ep;
    TVState tf, tb;

#pragma unroll
    for (int t = 0; t < NSIDE / NT; t++) {
        int i = tid + t * NT;
        sh.p[i] = 0.0f;
        sh.q[i] = 0.0f;
        sh.rcp_s[i] = 1.0f / (float)(i + 1);
    }
    if (tid == 0) { sh.s[NSIDE] = 0.0f; sh.s[NSIDE + 1] = 0.0f; }

    for (int it = 0; it < NITER; it++) {
        // ================= column phase: block b owns column b =============
#pragma unroll
        for (int t = 0; t < NSIDE / NT; t++) {
            int i = tid + t * NT;
            float xv = (it == 0) ? X[i * NSIDE + b] : g_xT[b * NSIDE + i];
            sh.s[i] = xv + sh.p[i];
        }
        {   // clear restart logs (only [QTR, HALF+1] is ever touched)
            int i = QTR + tid;
            if (i <= HALF) { sh.f_log[i] = 0; sh.b_log[i] = 0; }
        }
        __syncthreads();

        solve_line(sh, tid, tf, tb);

        {
            int eb = sh.se_b;
#pragma unroll
            for (int t = 0; t < NSIDE / NT; t++) {
                int i = tid + t * NT;
                float ov = (i >= eb) ? sh.ob[i] : sh.o[i];
                sh.p[i] = sh.s[i] - ov;
                g_y[i * NSIDE + b] = ov;     // strided column write
            }
        }
        gridbar(ep, false);

        // ================= row phase: block b owns row b ===================
#pragma unroll
        for (int t = 0; t < NSIDE / NT; t++) {
            int i = tid + t * NT;
            sh.s[i] = g_y[b * NSIDE + i] + sh.q[i];
        }
        {
            int i = QTR + tid;
            if (i <= HALF) { sh.f_log[i] = 0; sh.b_log[i] = 0; }
        }
        __syncthreads();

        solve_line(sh, tid, tf, tb);

        float m = 0.0f;
        {
            int eb = sh.se_b;
#pragma unroll
            for (int t = 0; t < NSIDE / NT; t++) {
                int i = tid + t * NT;
                float ov = (i >= eb) ? sh.ob[i] : sh.o[i];
                float sv = sh.s[i];
                float qo = sh.q[i];
                sh.q[i] = sv - ov;
                x[b * NSIDE + i] = ov;       // d_out (coalesced)
                g_xT[i * NSIDE + b] = ov;    // transposed mirror
                m = fmaxf(m, fabsf((sv - qo) - ov));   // |y - x2|
            }
        }
#pragma unroll
        for (int off = 16; off; off >>= 1)
            m = fmaxf(m, __shfl_xor_sync(0xffffffffu, m, off));
        if (lane == 0) sh.swm[wid] = m;
        __syncthreads();
        if (tid == 0) {
            float mm = fmaxf(fmaxf(sh.swm[0], sh.swm[1]),
                             fmaxf(sh.swm[2], sh.swm[3]));
            atomicMax(&g_accbits, __float_as_int(mm));
        }

        gridbar(ep, true);
        if (g_stop) break;                   // DR converged
    }
}

extern "C" void kernel_launch(void* const* d_in, const int* in_sizes, int n_in,
                              void* d_out, int out_size)
{
    const float* X = (const float*)d_in[0];
    float* x = (float*)d_out;
    tv2d_persistent<<<NB, NT>>>(X, x);
}

// round 7
// speedup vs baseline: 3.0201x; 1.1099x over previous
#include <cuda_runtime.h>
#include <cuda_bf16.h>

#define NSIDE 256
#define NB    256
#define NT    256     // 8 warps: 8 scanner threads (4 fwd, 4 bwd)
#define LAM   0.05f   // STEP = ALPHA/2
#define TOLV  0.01f
#define NITER 35
#define HALF  (NSIDE / 2)
#define SEG   32      // elements per speculative segment
#define NSEGS (HALF / SEG)   // 4 per direction
#define BIGK  (NSIDE + 8)

// Cross-block exchange buffers.
__device__ float g_y [NSIDE * NSIDE];
__device__ float g_xT[NSIDE * NSIDE];

// Atomic grid barrier.
__device__ unsigned          g_cnt;
__device__ volatile unsigned g_ep;
__device__ volatile int      g_stop;
__device__ int               g_accbits;

struct TVState {
    int k, k0, kminus, kplus;
    float vmin, vmax, umin, umax, ynext;
};

template<bool FWD>
__device__ __forceinline__ float ldy(const float* __restrict__ s, int i) {
    return FWD ? s[i] : s[NSIDE - 1 - i];
}
template<bool FWD>
__device__ __forceinline__ void sto(float* __restrict__ out, int i, float v) {
    if (FWD) out[i] = v; else out[NSIDE - 1 - i] = v;
}

// Fresh Condat state positioned at `pos` (pos < NSIDE-1).
template<bool FWD>
__device__ __forceinline__ void init_state_at(const float* __restrict__ s,
                                              TVState& t, int pos)
{
    float y0 = ldy<FWD>(s, pos), y1 = ldy<FWD>(s, pos + 1);
    t.k = pos; t.k0 = pos; t.kminus = pos; t.kplus = pos;
    t.vmin = y0 - LAM; t.vmax = y0 + LAM;
    t.umin = LAM; t.umax = -LAM;
    t.ynext = y1;
}

// Exact 1D TV prox (Condat 2013), resumable.
// MODE 0: plain. MODE 1: record restart (pos,dir) into log.
// MODE 2: after each restart at pos p with dir d, if log[p]==d the state
//         provably equals the spec scanner's post-restart state -> return 1.
template<bool FWD, int MODE>
__device__ int tv_scan(const float* __restrict__ s, float* __restrict__ out,
                       const float* __restrict__ rcp, TVState& t,
                       int kstop, int k0stop, unsigned char* log)
{
    const float lam = LAM, mlam = -LAM, twolam = 2.0f * LAM;
    for (;;) {
        if (t.k0 >= k0stop) return 0;
        while (t.k == NSIDE - 1) {            // termination (kstop==NSIDE only)
            if (t.umin < 0.0f) {
                do { sto<FWD>(out, t.k0++, t.vmin); } while (t.k0 <= t.kminus);
                t.k = t.k0; t.kminus = t.k0;
                t.vmin = ldy<FWD>(s, t.k);
                t.umin = lam;
                t.umax = t.vmin + lam - t.vmax;
            } else if (t.umax > 0.0f) {
                do { sto<FWD>(out, t.k0++, t.vmax); } while (t.k0 <= t.kplus);
                t.k = t.k0; t.kplus = t.k0;
                t.vmax = ldy<FWD>(s, t.k);
                t.umax = mlam;
                t.umin = t.vmax - lam - t.vmin;
            } else {
                t.vmin += t.umin * rcp[t.k - t.k0];
                do { sto<FWD>(out, t.k0++, t.vmin); } while (t.k0 <= t.k);
                t.k0 = BIGK;                   // done
                return 0;
            }
            t.ynext = ldy<FWD>(s, t.k + 1);
            if (t.k0 >= k0stop) return 0;
        }
        if (t.k >= kstop) return 0;
        float yspec = ldy<FWD>(s, t.k + 2);   // speculative prefetch (padded)
        float a  = t.umin + (t.ynext - t.vmin);
        float bb = t.umax + (t.ynext - t.vmax);
        if (a < mlam) {                       // negative jump
            do { sto<FWD>(out, t.k0++, t.vmin); } while (t.k0 <= t.kminus);
            bool fast = (t.k0 == t.k + 1);
            t.k = t.k0; t.kminus = t.k0; t.kplus = t.k0;
            float nv = fast ? t.ynext : ldy<FWD>(s, t.k0);
            t.ynext  = fast ? yspec   : ldy<FWD>(s, t.k0 + 1);
            t.vmin = nv; t.vmax = nv + twolam;
            t.umin = lam; t.umax = mlam;
            if (MODE == 1) log[t.k0] = 1;
            if (MODE == 2) { if (log[t.k0] == 1) return 1; }
        } else if (bb > lam) {                // positive jump
            do { sto<FWD>(out, t.k0++, t.vmax); } while (t.k0 <= t.kplus);
            bool fast = (t.k0 == t.k + 1);
            t.k = t.k0; t.kminus = t.k0; t.kplus = t.k0;
            float nv = fast ? t.ynext : ldy<FWD>(s, t.k0);
            t.ynext  = fast ? yspec   : ldy<FWD>(s, t.k0 + 1);
            t.vmax = nv; t.vmin = nv - twolam;
            t.umin = lam; t.umax = mlam;
            if (MODE == 1) log[t.k0] = 2;
            if (MODE == 2) { if (log[t.k0] == 2) return 1; }
        } else {                              // no jump
            t.k++;
            t.umin = a; t.umax = bb;
            if (a >= lam)   { t.vmin += (a - lam)  * rcp[t.k - t.k0]; t.umin = lam;  t.kminus = t.k; }
            if (bb <= mlam) { t.vmax += (bb + lam) * rcp[t.k - t.k0]; t.umax = mlam; t.kplus  = t.k; }
            t.ynext = yspec;
        }
    }
}

// Grid barrier (R2 atomic design — measured best).
__device__ __forceinline__ void gridbar(unsigned& ep, bool doCommit)
{
    __syncthreads();
    ep += 1;
    if (threadIdx.x == 0) {
        __threadfence();
        unsigned old = atomicAdd(&g_cnt, 1u);
        if (old == NB - 1) {
            __threadfence();
            if (doCommit) {
                g_stop = (__int_as_float(g_accbits) < TOLV) ? 1 : 0;
                g_accbits = 0;
            }
            atomicExch(&g_cnt, 0u);
            __threadfence();
            g_ep = ep;
        } else {
            while ((int)(g_ep - ep) < 0) { }
        }
    }
    __syncthreads();
    __threadfence();
}

struct SharedBlk {
    float s[NSIDE + 2];
    float o[NSIDE];
    float ob[NSIDE];
    float p[NSIDE];
    float q[NSIDE];
    float rcp_s[NSIDE];
    unsigned char f_log[HALF + 2];
    unsigned char b_log[HALF + 2];
    TVState sf_end[NSEGS], sb_end[NSEGS];   // index 1..NSEGS-1 used
    int   se_b;
    float swm[NT / 32];
};

// One full line solve using 8 scanner threads (one per warp).
// Forward: warps 0..3 (warp0 exact, warps 1-3 speculative on segments 1-3).
// Backward: warps 4..7 mirrored on the reversed line.
__device__ __forceinline__ void solve_line(SharedBlk& sh, int tid,
                                           TVState& tf, TVState& tb)
{
    const int w = tid >> 5;
    // ---- stage A: eight parallel scans ----
    if ((tid & 31) == 0) {
        if (w == 0) {                    // exact forward on [0, SEG)
            init_state_at<true>(sh.s, tf, 0);
            tv_scan<true, 0>(sh.s, sh.o, sh.rcp_s, tf, SEG, BIGK, 0);
        } else if (w < NSEGS) {          // speculative forward, segment w
            TVState t; init_state_at<true>(sh.s, t, w * SEG);
            tv_scan<true, 1>(sh.s, sh.o, sh.rcp_s, t, (w + 1) * SEG, BIGK, sh.f_log);
            sh.sf_end[w] = t;
        } else if (w == NSEGS) {         // exact backward on [0, SEG)b
            init_state_at<false>(sh.s, tb, 0);
            tv_scan<false, 0>(sh.s, sh.ob, sh.rcp_s, tb, SEG, BIGK, 0);
        } else {                         // speculative backward, segment w-NSEGS
            int j = w - NSEGS;
            TVState t; init_state_at<false>(sh.s, t, j * SEG);
            tv_scan<false, 1>(sh.s, sh.ob, sh.rcp_s, t, (j + 1) * SEG, BIGK, sh.b_log);
            sh.sb_end[j] = t;
        }
    }
    __syncthreads();

    // ---- stage B: chained coupling fixups (fwd & bwd concurrently) ----
    if (tid == 0) {
        while (tv_scan<true, 2>(sh.s, sh.o, sh.rcp_s, tf, HALF, BIGK, sh.f_log)) {
            int j = (tf.k0 - 1) / SEG;   // segment that wrote log[tf.k0]
            tf = sh.sf_end[j];           // provably equal state: adopt tail
            if (tf.k >= HALF) break;
        }
    } else if (tid == NSEGS * 32) {
        while (tv_scan<false, 2>(sh.s, sh.ob, sh.rcp_s, tb, HALF, BIGK, sh.b_log)) {
            int j = (tb.k0 - 1) / SEG;
            tb = sh.sb_end[j];
            if (tb.k >= HALF) break;
        }
        sh.se_b = NSIDE - tb.k0;         // first finalized backward position
    }
    __syncthreads();

    // ---- stage C: forward closes the middle gap ----
    if (tid == 0)
        tv_scan<true, 0>(sh.s, sh.o, sh.rcp_s, tf, NSIDE, sh.se_b, 0);
    __syncthreads();
}

__global__ void __launch_bounds__(NT)
tv2d_persistent(const float* __restrict__ X, float* __restrict__ x)
{
    __shared__ SharedBlk sh;
    const int b = blockIdx.x;
    const int tid = threadIdx.x;
    const int lane = tid & 31;
    const int wid = tid >> 5;
    unsigned ep = g_ep;
    TVState tf, tb;

    {
        int i = tid;
        sh.p[i] = 0.0f;
        sh.q[i] = 0.0f;
        sh.rcp_s[i] = 1.0f / (float)(i + 1);
    }
    if (tid == 0) { sh.s[NSIDE] = 0.0f; sh.s[NSIDE + 1] = 0.0f; }

    for (int it = 0; it < NITER; it++) {
        // ================= column phase: block b owns column b =============
        {
            int i = tid;
            float xv = (it == 0) ? X[i * NSIDE + b] : g_xT[b * NSIDE + i];
            sh.s[i] = xv + sh.p[i];
            if (i <= HALF - SEG) {        // clear restart logs [SEG, HALF]
                sh.f_log[SEG + i] = 0;
                sh.b_log[SEG + i] = 0;
            }
        }
        __syncthreads();

        solve_line(sh, tid, tf, tb);

        {
            int eb = sh.se_b;
            int i = tid;
            float ov = (i >= eb) ? sh.ob[i] : sh.o[i];
            sh.p[i] = sh.s[i] - ov;
            g_y[i * NSIDE + b] = ov;      // strided column write
        }
        gridbar(ep, false);

        // ================= row phase: block b owns row b ===================
        {
            int i = tid;
            sh.s[i] = g_y[b * NSIDE + i] + sh.q[i];
            if (i <= HALF - SEG) {
                sh.f_log[SEG + i] = 0;
                sh.b_log[SEG + i] = 0;
            }
        }
        __syncthreads();

        solve_line(sh, tid, tf, tb);

        float m = 0.0f;
        {
            int eb = sh.se_b;
            int i = tid;
            float ov = (i >= eb) ? sh.ob[i] : sh.o[i];
            float sv = sh.s[i];
            float qo = sh.q[i];
            sh.q[i] = sv - ov;
            x[b * NSIDE + i] = ov;        // d_out (coalesced)
            g_xT[i * NSIDE + b] = ov;     // transposed mirror
            m = fabsf((sv - qo) - ov);    // |y - x2|
        }
#pragma unroll
        for (int off = 16; off; off >>= 1)
            m = fmaxf(m, __shfl_xor_sync(0xffffffffu, m, off));
        if (lane == 0) sh.swm[wid] = m;
        __syncthreads();
        if (tid == 0) {
            float mm = sh.swm[0];
#pragma unroll
            for (int t = 1; t < NT / 32; t++) mm = fmaxf(mm, sh.swm[t]);
            atomicMax(&g_accbits, __float_as_int(mm));
        }

        gridbar(ep, true);
        if (g_stop) break;                // DR converged
    }
}

extern "C" void kernel_launch(void* const* d_in, const int* in_sizes, int n_in,
                              void* d_out, int out_size)
{
    const float* X = (const float*)d_in[0];
    float* x = (float*)d_out;
    tv2d_persistent<<<NB, NT>>>(X, x);
}

// round 8
// speedup vs baseline: 3.1289x; 1.0360x over previous
#include <cuda_runtime.h>
#include <cuda_bf16.h>

#define NSIDE 256
#define NB    128     // blocks; each owns 2 lines
#define NT    1024    // 2 lines x 16 scanner warps
#define NTL   512     // threads per line
#define LAM   0.05f   // STEP = ALPHA/2
#define TOLV  0.01f
#define NITER 35
#define HALF  (NSIDE / 2)
#define SEG   16      // elements per speculative segment
#define NSEGS (HALF / SEG)   // 8 per direction
#define BIGK  (NSIDE + 8)

// Cross-block exchange buffers.
__device__ float g_y [NSIDE * NSIDE];
__device__ float g_xT[NSIDE * NSIDE];

// Atomic grid barrier.
__device__ unsigned          g_cnt;
__device__ volatile unsigned g_ep;
__device__ volatile int      g_stop;
__device__ int               g_accbits;

struct TVState {
    int k, k0, kminus, kplus;
    float vmin, vmax, umin, umax, ynext;
};

template<bool FWD>
__device__ __forceinline__ float ldy(const float* __restrict__ s, int i) {
    return FWD ? s[i] : s[NSIDE - 1 - i];
}
template<bool FWD>
__device__ __forceinline__ void sto(float* __restrict__ out, int i, float v) {
    if (FWD) out[i] = v; else out[NSIDE - 1 - i] = v;
}

// Fresh Condat state positioned at `pos` (pos < NSIDE-1).
template<bool FWD>
__device__ __forceinline__ void init_state_at(const float* __restrict__ s,
                                              TVState& t, int pos)
{
    float y0 = ldy<FWD>(s, pos), y1 = ldy<FWD>(s, pos + 1);
    t.k = pos; t.k0 = pos; t.kminus = pos; t.kplus = pos;
    t.vmin = y0 - LAM; t.vmax = y0 + LAM;
    t.umin = LAM; t.umax = -LAM;
    t.ynext = y1;
}

// Exact 1D TV prox (Condat 2013), resumable.
// MODE 0: plain. MODE 1: record restart (pos,dir) into log.
// MODE 2: after each restart at pos p with dir d, if log[p]==d the state
//         provably equals the spec scanner's post-restart state -> return 1.
template<bool FWD, int MODE>
__device__ int tv_scan(const float* __restrict__ s, float* __restrict__ out,
                       const float* __restrict__ rcp, TVState& t,
                       int kstop, int k0stop, unsigned char* log)
{
    const float lam = LAM, mlam = -LAM, twolam = 2.0f * LAM;
    for (;;) {
        if (t.k0 >= k0stop) return 0;
        while (t.k == NSIDE - 1) {            // termination (kstop==NSIDE only)
            if (t.umin < 0.0f) {
                do { sto<FWD>(out, t.k0++, t.vmin); } while (t.k0 <= t.kminus);
                t.k = t.k0; t.kminus = t.k0;
                t.vmin = ldy<FWD>(s, t.k);
                t.umin = lam;
                t.umax = t.vmin + lam - t.vmax;
            } else if (t.umax > 0.0f) {
                do { sto<FWD>(out, t.k0++, t.vmax); } while (t.k0 <= t.kplus);
                t.k = t.k0; t.kplus = t.k0;
                t.vmax = ldy<FWD>(s, t.k);
                t.umax = mlam;
                t.umin = t.vmax - lam - t.vmin;
            } else {
                t.vmin += t.umin * rcp[t.k - t.k0];
                do { sto<FWD>(out, t.k0++, t.vmin); } while (t.k0 <= t.k);
                t.k0 = BIGK;                   // done
                return 0;
            }
            t.ynext = ldy<FWD>(s, t.k + 1);
            if (t.k0 >= k0stop) return 0;
        }
        if (t.k >= kstop) return 0;
        float yspec = ldy<FWD>(s, t.k + 2);   // speculative prefetch (padded)
        float a  = t.umin + (t.ynext - t.vmin);
        float bb = t.umax + (t.ynext - t.vmax);
        if (a < mlam) {                       // negative jump
            do { sto<FWD>(out, t.k0++, t.vmin); } while (t.k0 <= t.kminus);
            bool fast = (t.k0 == t.k + 1);
            t.k = t.k0; t.kminus = t.k0; t.kplus = t.k0;
            float nv = fast ? t.ynext : ldy<FWD>(s, t.k0);
            t.ynext  = fast ? yspec   : ldy<FWD>(s, t.k0 + 1);
            t.vmin = nv; t.vmax = nv + twolam;
            t.umin = lam; t.umax = mlam;
            if (MODE == 1) log[t.k0] = 1;
            if (MODE == 2) { if (log[t.k0] == 1) return 1; }
        } else if (bb > lam) {                // positive jump
            do { sto<FWD>(out, t.k0++, t.vmax); } while (t.k0 <= t.kplus);
            bool fast = (t.k0 == t.k + 1);
            t.k = t.k0; t.kminus = t.k0; t.kplus = t.k0;
            float nv = fast ? t.ynext : ldy<FWD>(s, t.k0);
            t.ynext  = fast ? yspec   : ldy<FWD>(s, t.k0 + 1);
            t.vmax = nv; t.vmin = nv - twolam;
            t.umin = lam; t.umax = mlam;
            if (MODE == 1) log[t.k0] = 2;
            if (MODE == 2) { if (log[t.k0] == 2) return 1; }
        } else {                              // no jump
            t.k++;
            t.umin = a; t.umax = bb;
            if (a >= lam)   { t.vmin += (a - lam)  * rcp[t.k - t.k0]; t.umin = lam;  t.kminus = t.k; }
            if (bb <= mlam) { t.vmax += (bb + lam) * rcp[t.k - t.k0]; t.umax = mlam; t.kplus  = t.k; }
            t.ynext = yspec;
        }
    }
}

// Grid barrier (atomic design, 128 arrivals).
__device__ __forceinline__ void gridbar(unsigned& ep, bool doCommit)
{
    __syncthreads();
    ep += 1;
    if (threadIdx.x == 0) {
        __threadfence();
        unsigned old = atomicAdd(&g_cnt, 1u);
        if (old == NB - 1) {
            __threadfence();
            if (doCommit) {
                g_stop = (__int_as_float(g_accbits) < TOLV) ? 1 : 0;
                g_accbits = 0;
            }
            atomicExch(&g_cnt, 0u);
            __threadfence();
            g_ep = ep;
        } else {
            while ((int)(g_ep - ep) < 0) { }
        }
    }
    __syncthreads();
    __threadfence();
}

struct LineBlk {
    float s[NSIDE + 2];
    float o[NSIDE];
    float ob[NSIDE];
    float p[NSIDE];
    float q[NSIDE];
    unsigned char f_log[HALF + 2];
    unsigned char b_log[HALF + 2];
    TVState sf_end[NSEGS], sb_end[NSEGS];   // index 1..NSEGS-1 used
    int   se_b;
};

// One full line solve using 16 scanner threads (one per warp within the line's
// 512 threads). Forward: warps 0..7 (warp0 exact). Backward: warps 8..15.
__device__ __forceinline__ void solve_line(LineBlk& sh, const float* rcp,
                                           int lt, TVState& tf, TVState& tb)
{
    const int w = lt >> 5;
    // ---- stage A: sixteen parallel scans ----
    if ((lt & 31) == 0) {
        if (w == 0) {                    // exact forward on [0, SEG)
            init_state_at<true>(sh.s, tf, 0);
            tv_scan<true, 0>(sh.s, sh.o, rcp, tf, SEG, BIGK, 0);
        } else if (w < NSEGS) {          // speculative forward, segment w
            TVState t; init_state_at<true>(sh.s, t, w * SEG);
            tv_scan<true, 1>(sh.s, sh.o, rcp, t, (w + 1) * SEG, BIGK, sh.f_log);
            sh.sf_end[w] = t;
        } else if (w == NSEGS) {         // exact backward on [0, SEG)b
            init_state_at<false>(sh.s, tb, 0);
            tv_scan<false, 0>(sh.s, sh.ob, rcp, tb, SEG, BIGK, 0);
        } else {                         // speculative backward, segment w-NSEGS
            int j = w - NSEGS;
            TVState t; init_state_at<false>(sh.s, t, j * SEG);
            tv_scan<false, 1>(sh.s, sh.ob, rcp, t, (j + 1) * SEG, BIGK, sh.b_log);
            sh.sb_end[j] = t;
        }
    }
    __syncthreads();

    // ---- stage B: chained coupling fixups (fwd & bwd concurrently) ----
    if (lt == 0) {
        while (tv_scan<true, 2>(sh.s, sh.o, rcp, tf, HALF, BIGK, sh.f_log)) {
            int j = (tf.k0 - 1) / SEG;   // segment that wrote log[tf.k0]
            tf = sh.sf_end[j];           // provably equal state: adopt tail
            if (tf.k >= HALF) break;
        }
    } else if (lt == NSEGS * 32) {
        while (tv_scan<false, 2>(sh.s, sh.ob, rcp, tb, HALF, BIGK, sh.b_log)) {
            int j = (tb.k0 - 1) / SEG;
            tb = sh.sb_end[j];
            if (tb.k >= HALF) break;
        }
        sh.se_b = NSIDE - tb.k0;         // first finalized backward position
    }
    __syncthreads();

    // ---- stage C: forward closes the middle gap ----
    if (lt == 0)
        tv_scan<true, 0>(sh.s, sh.o, rcp, tf, NSIDE, sh.se_b, 0);
    __syncthreads();
}

__global__ void __launch_bounds__(NT, 1)
tv2d_persistent(const float* __restrict__ X, float* __restrict__ x)
{
    __shared__ LineBlk sh[2];
    __shared__ float rcp_s[NSIDE];
    __shared__ float swm[NT / 32];
    const int tid  = threadIdx.x;
    const int line = tid >> 9;           // 0 or 1
    const int lt   = tid & (NTL - 1);    // tid within line
    const int lane = tid & 31;
    const int b    = blockIdx.x * 2 + line;   // owned column/row index
    unsigned ep = g_ep;
    TVState tf, tb;
    LineBlk& L = sh[line];

    if (lt < NSIDE) {
        L.p[lt] = 0.0f;
        L.q[lt] = 0.0f;
        if (line == 0) rcp_s[lt] = 1.0f / (float)(lt + 1);
    }
    if (lt == 0) { L.s[NSIDE] = 0.0f; L.s[NSIDE + 1] = 0.0f; }

    for (int it = 0; it < NITER; it++) {
        // ================= column phase: line owns column b =================
        if (lt < NSIDE) {
            float xv = (it == 0) ? X[lt * NSIDE + b] : g_xT[b * NSIDE + lt];
            L.s[lt] = xv + L.p[lt];
            if (lt <= HALF - SEG) {       // clear restart logs [SEG, HALF]
                L.f_log[SEG + lt] = 0;
                L.b_log[SEG + lt] = 0;
            }
        }
        __syncthreads();

        solve_line(L, rcp_s, lt, tf, tb);

        if (lt < NSIDE) {
            int eb = L.se_b;
            float ov = (lt >= eb) ? L.ob[lt] : L.o[lt];
            L.p[lt] = L.s[lt] - ov;
            g_y[lt * NSIDE + b] = ov;     // strided column write
        }
        gridbar(ep, false);

        // ================= row phase: line owns row b =======================
        if (lt < NSIDE) {
            L.s[lt] = g_y[b * NSIDE + lt] + L.q[lt];
            if (lt <= HALF - SEG) {
                L.f_log[SEG + lt] = 0;
                L.b_log[SEG + lt] = 0;
            }
        }
        __syncthreads();

        solve_line(L, rcp_s, lt, tf, tb);

        float m = 0.0f;
        if (lt < NSIDE) {
            int eb = L.se_b;
            float ov = (lt >= eb) ? L.ob[lt] : L.o[lt];
            float sv = L.s[lt];
            float qo = L.q[lt];
            L.q[lt] = sv - ov;
            x[b * NSIDE + lt] = ov;       // d_out (coalesced)
            g_xT[lt * NSIDE + b] = ov;    // transposed mirror
            m = fabsf((sv - qo) - ov);    // |y - x2|
        }
#pragma unroll
        for (int off = 16; off; off >>= 1)
            m = fmaxf(m, __shfl_xor_sync(0xffffffffu, m, off));
        if (lane == 0) swm[tid >> 5] = m;
        __syncthreads();
        if (tid == 0) {
            float mm = swm[0];
#pragma unroll
            for (int t = 1; t < NT / 32; t++) mm = fmaxf(mm, swm[t]);
            atomicMax(&g_accbits, __float_as_int(mm));
        }

        gridbar(ep, true);
        if (g_stop) break;                // DR converged
    }
}

extern "C" void kernel_launch(void* const* d_in, const int* in_sizes, int n_in,
                              void* d_out, int out_size)
{
    const float* X = (const float*)d_in[0];
    float* x = (float*)d_out;
    tv2d_persistent<<<NB, NT>>>(X, x);
}

// round 9
// speedup vs baseline: 3.1484x; 1.0062x over previous
#include <cuda_runtime.h>
#include <cuda_bf16.h>

#define NSIDE 256
#define NB    128     // blocks; each owns 2 lines
#define NT    1024    // 2 lines x 16 scanner warps
#define NTL   512     // threads per line
#define LAM   0.05f   // STEP = ALPHA/2
#define TOLV  0.01f
#define NITER 35
#define HALF  (NSIDE / 2)
#define SEG   16      // elements per speculative segment
#define NSEGS (HALF / SEG)   // 8 per direction
#define BIGK  (NSIDE + 8)

// Cross-block exchange buffers.
__device__ float g_y [NSIDE * NSIDE];
__device__ float g_xT[NSIDE * NSIDE];

// Atomic grid barrier.
__device__ unsigned          g_cnt;
__device__ volatile unsigned g_ep;
__device__ volatile int      g_stop;
__device__ int               g_accbits;

struct TVState {
    int k, k0, kminus, kplus;
    float vmin, vmax, umin, umax, ynext;
};

template<bool FWD>
__device__ __forceinline__ float ldy(const float* __restrict__ s, int i) {
    return FWD ? s[i] : s[NSIDE - 1 - i];
}
template<bool FWD>
__device__ __forceinline__ void sto(float* __restrict__ out, int i, float v) {
    if (FWD) out[i] = v; else out[NSIDE - 1 - i] = v;
}

// Fresh Condat state positioned at `pos` (pos < NSIDE-1).
template<bool FWD>
__device__ __forceinline__ void init_state_at(const float* __restrict__ s,
                                              TVState& t, int pos)
{
    float y0 = ldy<FWD>(s, pos), y1 = ldy<FWD>(s, pos + 1);
    t.k = pos; t.k0 = pos; t.kminus = pos; t.kplus = pos;
    t.vmin = y0 - LAM; t.vmax = y0 + LAM;
    t.umin = LAM; t.umax = -LAM;
    t.ynext = y1;
}

// Exact 1D TV prox (Condat 2013), resumable.
// MODE 0: plain. MODE 1: record restart (pos,dir) into log.
// MODE 2: after each restart at pos p with dir d, if log[p]==d the state
//         provably equals the spec scanner's post-restart state -> return 1.
template<bool FWD, int MODE>
__device__ int tv_scan(const float* __restrict__ s, float* __restrict__ out,
                       const float* __restrict__ rcp, TVState& t,
                       int kstop, int k0stop, unsigned char* log)
{
    const float lam = LAM, mlam = -LAM, twolam = 2.0f * LAM;
    for (;;) {
        if (t.k0 >= k0stop) return 0;
        while (t.k == NSIDE - 1) {            // termination (kstop==NSIDE only)
            if (t.umin < 0.0f) {
                do { sto<FWD>(out, t.k0++, t.vmin); } while (t.k0 <= t.kminus);
                t.k = t.k0; t.kminus = t.k0;
                t.vmin = ldy<FWD>(s, t.k);
                t.umin = lam;
                t.umax = t.vmin + lam - t.vmax;
            } else if (t.umax > 0.0f) {
                do { sto<FWD>(out, t.k0++, t.vmax); } while (t.k0 <= t.kplus);
                t.k = t.k0; t.kplus = t.k0;
                t.vmax = ldy<FWD>(s, t.k);
                t.umax = mlam;
                t.umin = t.vmax - lam - t.vmin;
            } else {
                t.vmin += t.umin * rcp[t.k - t.k0];
                do { sto<FWD>(out, t.k0++, t.vmin); } while (t.k0 <= t.k);
                t.k0 = BIGK;                   // done
                return 0;
            }
            t.ynext = ldy<FWD>(s, t.k + 1);
            if (t.k0 >= k0stop) return 0;
        }
        if (t.k >= kstop) return 0;
        float yspec = ldy<FWD>(s, t.k + 2);   // speculative prefetch (padded)
        float a  = t.umin + (t.ynext - t.vmin);
        float bb = t.umax + (t.ynext - t.vmax);
        if (a < mlam) {                       // negative jump
            do { sto<FWD>(out, t.k0++, t.vmin); } while (t.k0 <= t.kminus);
            bool fast = (t.k0 == t.k + 1);
            t.k = t.k0; t.kminus = t.k0; t.kplus = t.k0;
            float nv = fast ? t.ynext : ldy<FWD>(s, t.k0);
            t.ynext  = fast ? yspec   : ldy<FWD>(s, t.k0 + 1);
            t.vmin = nv; t.vmax = nv + twolam;
            t.umin = lam; t.umax = mlam;
            if (MODE == 1) log[t.k0] = 1;
            if (MODE == 2) { if (log[t.k0] == 1) return 1; }
        } else if (bb > lam) {                // positive jump
            do { sto<FWD>(out, t.k0++, t.vmax); } while (t.k0 <= t.kplus);
            bool fast = (t.k0 == t.k + 1);
            t.k = t.k0; t.kminus = t.k0; t.kplus = t.k0;
            float nv = fast ? t.ynext : ldy<FWD>(s, t.k0);
            t.ynext  = fast ? yspec   : ldy<FWD>(s, t.k0 + 1);
            t.vmax = nv; t.vmin = nv - twolam;
            t.umin = lam; t.umax = mlam;
            if (MODE == 1) log[t.k0] = 2;
            if (MODE == 2) { if (log[t.k0] == 2) return 1; }
        } else {                              // no jump
            t.k++;
            t.umin = a; t.umax = bb;
            if (a >= lam)   { t.vmin += (a - lam)  * rcp[t.k - t.k0]; t.umin = lam;  t.kminus = t.k; }
            if (bb <= mlam) { t.vmax += (bb + lam) * rcp[t.k - t.k0]; t.umax = mlam; t.kplus  = t.k; }
            t.ynext = yspec;
        }
    }
}

// Grid barrier (atomic design, 128 arrivals). Writer threads (haveIO) fence
// before arrival; only they fence after release (they do the global loads).
__device__ __forceinline__ void gridbar(unsigned& ep, bool doCommit, bool haveIO)
{
    if (haveIO) __threadfence();
    __syncthreads();
    ep += 1;
    if (threadIdx.x == 0) {
        unsigned old = atomicAdd(&g_cnt, 1u);
        if (old == NB - 1) {
            __threadfence();
            if (doCommit) {
                g_stop = (__int_as_float(g_accbits) < TOLV) ? 1 : 0;
                g_accbits = 0;
            }
            atomicExch(&g_cnt, 0u);
            __threadfence();
            g_ep = ep;
        } else {
            while ((int)(g_ep - ep) < 0) { }
        }
    }
    __syncthreads();
    if (haveIO) __threadfence();
}

struct LineBlk {
    float s[NSIDE + 2];
    float o[NSIDE];
    float ob[NSIDE];
    float p[NSIDE];
    float q[NSIDE];
    unsigned char f_log[HALF + 2];
    unsigned char b_log[HALF + 2];
    TVState sf_end[NSEGS], sb_end[NSEGS];   // index 1..NSEGS-1 used
    int f_done[NSEGS];                      // per-segment publish flags
    int b_done[NSEGS];
    int se_done;
    int se_b;
};

#define VOL(x) (*(volatile int*)&(x))

// One full line solve using 16 scanner threads (one per warp within the line's
// 512 threads). No intra-stage __syncthreads: spec scanners publish per-segment
// flags; the exact checkers pipeline behind them.
__device__ __forceinline__ void solve_line(LineBlk& sh, const float* rcp,
                                           int lt, TVState& tf, TVState& tb)
{
    const int w = lt >> 5;
    if ((lt & 31) != 0) return;

    if (w == 0) {
        // ---- exact forward [0, SEG), then pipelined coupling fixup ----
        init_state_at<true>(sh.s, tf, 0);
        tv_scan<true, 0>(sh.s, sh.o, rcp, tf, SEG, BIGK, 0);
        while (tf.k < HALF) {
            int j = tf.k / SEG;                    // 1..NSEGS-1
            while (!VOL(sh.f_done[j])) { }
            __threadfence_block();
            if (tv_scan<true, 2>(sh.s, sh.o, rcp, tf, (j + 1) * SEG, BIGK, sh.f_log)) {
                int jj = (tf.k0 - 1) / SEG;        // owner of matched restart
                tf = sh.sf_end[jj];                // provably equal: adopt tail
            }
        }
        // ---- stage C: close the middle gap (needs backward frontier) ----
        while (!VOL(sh.se_done)) { }
        __threadfence_block();
        tv_scan<true, 0>(sh.s, sh.o, rcp, tf, NSIDE, VOL(sh.se_b), 0);
    } else if (w < NSEGS) {
        // ---- speculative forward, segment w ----
        TVState t; init_state_at<true>(sh.s, t, w * SEG);
        tv_scan<true, 1>(sh.s, sh.o, rcp, t, (w + 1) * SEG, BIGK, sh.f_log);
        sh.sf_end[w] = t;
        __threadfence_block();
        VOL(sh.f_done[w]) = 1;
    } else if (w == NSEGS) {
        // ---- exact backward [0, SEG)b, then pipelined coupling fixup ----
        init_state_at<false>(sh.s, tb, 0);
        tv_scan<false, 0>(sh.s, sh.ob, rcp, tb, SEG, BIGK, 0);
        while (tb.k < HALF) {
            int j = tb.k / SEG;
            while (!VOL(sh.b_done[j])) { }
            __threadfence_block();
            if (tv_scan<false, 2>(sh.s, sh.ob, rcp, tb, (j + 1) * SEG, BIGK, sh.b_log)) {
                int jj = (tb.k0 - 1) / SEG;
                tb = sh.sb_end[jj];
            }
        }
        VOL(sh.se_b) = NSIDE - tb.k0;              // first finalized bwd position
        __threadfence_block();
        VOL(sh.se_done) = 1;
    } else {
        // ---- speculative backward, segment w-NSEGS ----
        int j = w - NSEGS;
        TVState t; init_state_at<false>(sh.s, t, j * SEG);
        tv_scan<false, 1>(sh.s, sh.ob, rcp, t, (j + 1) * SEG, BIGK, sh.b_log);
        sh.sb_end[j] = t;
        __threadfence_block();
        VOL(sh.b_done[j]) = 1;
    }
}

__global__ void __launch_bounds__(NT, 1)
tv2d_persistent(const float* __restrict__ X, float* __restrict__ x)
{
    __shared__ LineBlk sh[2];
    __shared__ float rcp_s[NSIDE];
    __shared__ float swm[NT / 32];
    const int tid  = threadIdx.x;
    const int line = tid >> 9;           // 0 or 1
    const int lt   = tid & (NTL - 1);    // tid within line
    const int lane = tid & 31;
    const int b    = blockIdx.x * 2 + line;   // owned column/row index
    const bool io  = (lt < NSIDE);
    unsigned ep = g_ep;
    TVState tf, tb;
    LineBlk& L = sh[line];

    if (io) {
        L.p[lt] = 0.0f;
        L.q[lt] = 0.0f;
        if (line == 0) rcp_s[lt] = 1.0f / (float)(lt + 1);
    }
    if (lt == 0) { L.s[NSIDE] = 0.0f; L.s[NSIDE + 1] = 0.0f; }

    for (int it = 0; it < NITER; it++) {
        // ================= column phase: line owns column b =================
        if (io) {
            float xv = (it == 0) ? X[lt * NSIDE + b] : g_xT[b * NSIDE + lt];
            L.s[lt] = xv + L.p[lt];
            if (lt <= HALF - SEG) {       // clear restart logs [SEG, HALF]
                L.f_log[SEG + lt] = 0;
                L.b_log[SEG + lt] = 0;
            }
            if (lt < NSEGS) { L.f_done[lt] = 0; L.b_done[lt] = 0; }
            if (lt == 0)    { L.se_done = 0; }
        }
        __syncthreads();

        solve_line(L, rcp_s, lt, tf, tb);
        __syncthreads();

        if (io) {
            int eb = L.se_b;
            float ov = (lt >= eb) ? L.ob[lt] : L.o[lt];
            L.p[lt] = L.s[lt] - ov;
            g_y[lt * NSIDE + b] = ov;     // strided column write
        }
        gridbar(ep, false, io);

        // ================= row phase: line owns row b =======================
        if (io) {
            L.s[lt] = g_y[b * NSIDE + lt] + L.q[lt];
            if (lt <= HALF - SEG) {
                L.f_log[SEG + lt] = 0;
                L.b_log[SEG + lt] = 0;
            }
            if (lt < NSEGS) { L.f_done[lt] = 0; L.b_done[lt] = 0; }
            if (lt == 0)    { L.se_done = 0; }
        }
        __syncthreads();

        solve_line(L, rcp_s, lt, tf, tb);
        __syncthreads();

        float m = 0.0f;
        if (io) {
            int eb = L.se_b;
            float ov = (lt >= eb) ? L.ob[lt] : L.o[lt];
            float sv = L.s[lt];
            float qo = L.q[lt];
            L.q[lt] = sv - ov;
            x[b * NSIDE + lt] = ov;       // d_out (coalesced)
            g_xT[lt * NSIDE + b] = ov;    // transposed mirror
            m = fabsf((sv - qo) - ov);    // |y - x2|
        }
#pragma unroll
        for (int off = 16; off; off >>= 1)
            m = fmaxf(m, __shfl_xor_sync(0xffffffffu, m, off));
        if (lane == 0) swm[tid >> 5] = m;
        __syncthreads();
        if (tid == 0) {
            float mm = swm[0];
#pragma unroll
            for (int t = 1; t < NT / 32; t++) mm = fmaxf(mm, swm[t]);
            atomicMax(&g_accbits, __float_as_int(mm));
        }

        gridbar(ep, true, io);
        if (g_stop) break;                // DR converged
    }
}

extern "C" void kernel_launch(void* const* d_in, const int* in_sizes, int n_in,
                              void* d_out, int out_size)
{
    const float* X = (const float*)d_in[0];
    float* x = (float*)d_out;
    tv2d_persistent<<<NB, NT>>>(X, x);
}